// round 5
// baseline (speedup 1.0000x reference)
#include <cuda_runtime.h>
#include <cuda_bf16.h>
#include <math.h>
#include <stdint.h>

#define BB 8
#define N1 8192
#define N2 2048
#define C1 128
#define C2 256
#define KIN1 384
#define O1 256
#define O2 128
#define BN_EPS 1e-5f
#define MIN_DIST 1e-10f
#define P_TOTAL (BB * N1)

// ---------------- scratch (no allocations allowed) ----------------
__device__ float g_p2T[BB * N2 * C2];                 // points2 transposed [B][N2][C2]
__device__ int   g_knn_idx[BB * N1 * 3];
__device__ float g_knn_w[BB * N1 * 3];
__device__ __nv_bfloat16 g_w0h[O1 * KIN1], g_w0l[O1 * KIN1];
__device__ __nv_bfloat16 g_w1h[O2 * O1],   g_w1l[O2 * O1];
__device__ __nv_bfloat16 g_x0h[BB * N1 * KIN1], g_x0l[BB * N1 * KIN1];  // conv0 B operand [n][k]
__device__ float g_y1T[BB * N1 * O1];                 // conv0 out (pre-BN), point-major [n][o]
__device__ float g_y2[BB * O2 * N1];                  // conv1 out (pre-BN), channel-major [o][n]
__device__ float g_sum0[O1], g_sq0[O1], g_sum1[O2], g_sq1[O2];
__device__ float g_scale0[O1], g_shift0[O1], g_scale1[O2], g_shift1[O2];

// ---------------- helpers ----------------
__device__ __forceinline__ uint32_t smem_u32(const void* p) {
    return (uint32_t)__cvta_generic_to_shared(p);
}
__device__ __forceinline__ void cp16(uint32_t dst, const void* src) {
    asm volatile("cp.async.ca.shared.global [%0], [%1], 16;" :: "r"(dst), "l"(src));
}
__device__ __forceinline__ void cp_commit() {
    asm volatile("cp.async.commit_group;" ::: "memory");
}
template <int N>
__device__ __forceinline__ void cp_wait() {
    asm volatile("cp.async.wait_group %0;" :: "n"(N) : "memory");
}
__device__ __forceinline__ void ldmx4(uint32_t a, uint32_t& r0, uint32_t& r1,
                                      uint32_t& r2, uint32_t& r3) {
    asm volatile("ldmatrix.sync.aligned.m8n8.x4.shared.b16 {%0,%1,%2,%3}, [%4];"
                 : "=r"(r0), "=r"(r1), "=r"(r2), "=r"(r3) : "r"(a));
}
__device__ __forceinline__ void mma16816(float* c, const uint32_t* a,
                                         uint32_t b0, uint32_t b1) {
    asm volatile("mma.sync.aligned.m16n8k16.row.col.f32.bf16.bf16.f32 "
                 "{%0,%1,%2,%3},{%4,%5,%6,%7},{%8,%9},{%0,%1,%2,%3};"
                 : "+f"(c[0]), "+f"(c[1]), "+f"(c[2]), "+f"(c[3])
                 : "r"(a[0]), "r"(a[1]), "r"(a[2]), "r"(a[3]), "r"(b0), "r"(b1));
}
__device__ __forceinline__ void split_bf16(float v, __nv_bfloat16& h, __nv_bfloat16& l) {
    h = __float2bfloat16(v);
    l = __float2bfloat16(v - __bfloat162float(h));
}

// ---------------- stats zero (graph replays!) ----------------
__global__ void init_stats_kernel() {
    int t = threadIdx.x;
    if (t < O1) { g_sum0[t] = 0.f; g_sq0[t] = 0.f; }
    if (t < O2) { g_sum1[t] = 0.f; g_sq1[t] = 0.f; }
}

// ---------------- weight split fp32 -> bf16 hi/lo ----------------
__global__ void split_w_kernel(const float* __restrict__ src,
                               __nv_bfloat16* __restrict__ dh,
                               __nv_bfloat16* __restrict__ dl, int n) {
    int i = blockIdx.x * blockDim.x + threadIdx.x;
    if (i < n) { __nv_bfloat16 h, l; split_bf16(src[i], h, l); dh[i] = h; dl[i] = l; }
}

// ---------------- transpose points2 [B,C2,N2] -> [B,N2,C2] ----------------
__global__ void transpose_p2_kernel(const float* __restrict__ p2) {
    __shared__ float tile[32][33];
    int b = blockIdx.z, c0 = blockIdx.y * 32, n0 = blockIdx.x * 32;
    int tx = threadIdx.x, ty = threadIdx.y;
    #pragma unroll
    for (int i = ty; i < 32; i += 8)
        tile[i][tx] = p2[(size_t)b * C2 * N2 + (size_t)(c0 + i) * N2 + n0 + tx];
    __syncthreads();
    #pragma unroll
    for (int i = ty; i < 32; i += 8)
        g_p2T[(size_t)b * N2 * C2 + (size_t)(n0 + i) * C2 + c0 + tx] = tile[tx][i];
}

// ---------------- transpose+split points1 [B,C1,N1] -> x0 [n][0..127] ----------------
__global__ void transpose_p1_kernel(const float* __restrict__ p1) {
    __shared__ float tile[32][33];
    int b = blockIdx.z, c0 = blockIdx.y * 32, n0 = blockIdx.x * 32;
    int tx = threadIdx.x, ty = threadIdx.y;
    #pragma unroll
    for (int i = ty; i < 32; i += 8)
        tile[i][tx] = p1[(size_t)b * C1 * N1 + (size_t)(c0 + i) * N1 + n0 + tx];
    __syncthreads();
    #pragma unroll
    for (int i = ty; i < 32; i += 8) {
        __nv_bfloat16 h, l; split_bf16(tile[tx][i], h, l);
        size_t idx = ((size_t)b * N1 + n0 + i) * KIN1 + c0 + tx;
        g_x0h[idx] = h; g_x0l[idx] = l;
    }
}

// ---------------- 3-NN ----------------
__global__ __launch_bounds__(128) void knn_kernel(const float* __restrict__ xyz1,
                                                  const float* __restrict__ xyz2) {
    __shared__ float4 s_p[N2];
    int b  = blockIdx.x >> 6;
    int n0 = (blockIdx.x & 63) << 7;
    const float* x2 = xyz2 + (size_t)b * N2 * 3;
    for (int j = threadIdx.x; j < N2; j += 128) {
        float px = x2[j * 3], py = x2[j * 3 + 1], pz = x2[j * 3 + 2];
        s_p[j] = make_float4(px, py, pz, px * px + py * py + pz * pz);
    }
    __syncthreads();
    int n = n0 + threadIdx.x;
    const float* q = xyz1 + ((size_t)b * N1 + n) * 3;
    float qx = q[0], qy = q[1], qz = q[2];
    float qn = qx * qx + qy * qy + qz * qz;
    float d0 = 3.4e38f, d1 = 3.4e38f, d2 = 3.4e38f;
    int   i0 = 0, i1 = 0, i2 = 0;
    #pragma unroll 4
    for (int j = 0; j < N2; j++) {
        float4 p = s_p[j];
        float t  = fmaf(qx, p.x, fmaf(qy, p.y, qz * p.z));
        float sq = qn + p.w - 2.f * t;
        if (sq < d2) {
            if (sq < d1) {
                d2 = d1; i2 = i1;
                if (sq < d0) { d1 = d0; i1 = i0; d0 = sq; i0 = j; }
                else         { d1 = sq; i1 = j; }
            } else { d2 = sq; i2 = j; }
        }
    }
    float e0 = fmaxf(sqrtf(fmaxf(d0, 0.f)), MIN_DIST);
    float e1 = fmaxf(sqrtf(fmaxf(d1, 0.f)), MIN_DIST);
    float e2 = fmaxf(sqrtf(fmaxf(d2, 0.f)), MIN_DIST);
    float w0 = 1.f / e0, w1 = 1.f / e1, w2 = 1.f / e2;
    float inv = 1.f / (w0 + w1 + w2);
    size_t on = ((size_t)b * N1 + n) * 3;
    g_knn_idx[on] = i0; g_knn_idx[on + 1] = i1; g_knn_idx[on + 2] = i2;
    g_knn_w[on] = w0 * inv; g_knn_w[on + 1] = w1 * inv; g_knn_w[on + 2] = w2 * inv;
}

// ---------------- interpolation -> x0 [n][128..383] bf16 split ----------------
__global__ __launch_bounds__(256) void interp_kernel() {
    __shared__ int   s_idx[96];
    __shared__ float s_w[96];
    int b  = blockIdx.x >> 8;
    int n0 = (blockIdx.x & 255) << 5;
    int t  = threadIdx.x;
    if (t < 96) {
        size_t base = ((size_t)b * N1 + n0) * 3 + t;
        s_idx[t] = g_knn_idx[base];
        s_w[t]   = g_knn_w[base];
    }
    __syncthreads();
    int c = t;
    #pragma unroll 4
    for (int p = 0; p < 32; p++) {
        int k = p * 3;
        const float* r0 = g_p2T + ((size_t)b * N2 + s_idx[k + 0]) * C2 + c;
        const float* r1 = g_p2T + ((size_t)b * N2 + s_idx[k + 1]) * C2 + c;
        const float* r2 = g_p2T + ((size_t)b * N2 + s_idx[k + 2]) * C2 + c;
        float v = fmaf(s_w[k], *r0, fmaf(s_w[k + 1], *r1, s_w[k + 2] * (*r2)));
        __nv_bfloat16 h, l; split_bf16(v, h, l);
        size_t idx = ((size_t)b * N1 + n0 + p) * KIN1 + C1 + c;
        g_x0h[idx] = h; g_x0l[idx] = l;
    }
}

// ---------------- mma.sync conv, per-chunk 3-set accumulation ----------------
// CTA 128x128, 8 warps (2x4 -> 64x32 each). K-chunk 64. Per chunk: tiles
// Ah, Al, Bh, Bl in SMEM (rows padded to 144 B), MMA sets (Ah,Bh)+(Ah,Bl)+(Al,Bh).
// LAYER 0: B tiles cp.async from pre-split g_x0h/g_x0l.
// LAYER 1: B tiles built in-kernel from fp32 g_y1T with BN0+ReLU+split (no midpass).
#define TS 18432
#define SMEM_MMA (8 * TS)

template <int LAYER>
__global__ void __launch_bounds__(256, 1) conv_mma_kernel(const float* __restrict__ bias) {
    constexpr int K   = (LAYER == 0) ? KIN1 : O1;
    constexpr int NCH = K / 64;
    extern __shared__ char smem[];
    uint32_t sb = smem_u32(smem);

    int tid  = threadIdx.x;
    int lane = tid & 31, wid = tid >> 5;
    int m_off = (wid >> 2) * 64;     // warp m-origin (o)
    int n_off = (wid & 3) * 32;      // warp n-origin (points)
    int b  = blockIdx.x >> 6;
    int n0 = (blockIdx.x & 63) << 7;
    int o0 = blockIdx.y << 7;

    const __nv_bfloat16* Wbase_h = ((LAYER == 0) ? g_w0h : g_w1h) + (size_t)o0 * K;
    const __nv_bfloat16* Wbase_l = ((LAYER == 0) ? g_w0l : g_w1l) + (size_t)o0 * K;
    const __nv_bfloat16* Xbase_h = g_x0h + ((size_t)b * N1 + n0) * K;   // LAYER 0 only
    const __nv_bfloat16* Xbase_l = g_x0l + ((size_t)b * N1 + n0) * K;
    const float*         Ybase   = g_y1T + ((size_t)b * N1 + n0) * O1;  // LAYER 1 only

    uint32_t lm_off = (uint32_t)(((lane & 7) + ((lane >> 3) & 1) * 8) * 144 + (lane >> 4) * 16);

    float acc[4][4][4];
    #pragma unroll
    for (int mi = 0; mi < 4; mi++)
        #pragma unroll
        for (int ni = 0; ni < 4; ni++)
            #pragma unroll
            for (int r = 0; r < 4; r++) acc[mi][ni][r] = 0.f;

    int ld_row = tid >> 3;           // cp.async: 32 rows per i-step
    int ld_seg = tid & 7;

    // stage s tiles: Ah = s*4*TS, Al = +TS, Bh = +2TS, Bl = +3TS
    auto issue_chunk_A = [&](int c, int buf) {
        int kk = c * 64;
        uint32_t Ah = sb + buf * 4 * TS;
        #pragma unroll
        for (int i = 0; i < 4; i++) {
            int row = ld_row + i * 32;
            uint32_t d = (uint32_t)(row * 144 + ld_seg * 16);
            cp16(Ah + d,      Wbase_h + (size_t)row * K + kk + ld_seg * 8);
            cp16(Ah + TS + d, Wbase_l + (size_t)row * K + kk + ld_seg * 8);
        }
    };
    auto issue_chunk_B0 = [&](int c, int buf) {
        int kk = c * 64;
        uint32_t Bh = sb + buf * 4 * TS + 2 * TS;
        #pragma unroll
        for (int i = 0; i < 4; i++) {
            int row = ld_row + i * 32;
            uint32_t d = (uint32_t)(row * 144 + ld_seg * 16);
            cp16(Bh + d,      Xbase_h + (size_t)row * K + kk + ld_seg * 8);
            cp16(Bh + TS + d, Xbase_l + (size_t)row * K + kk + ld_seg * 8);
        }
    };

    // LAYER 1 B-regs pipeline: each thread owns 8 float4 (128 rows x 16 f4-segs)
    int y_row = tid >> 4;            // 0..15 (x8 i-steps of 16 rows)
    int y_seg = tid & 15;            // 0..15 -> 4 floats each
    float4 yreg[8];
    auto loadB1 = [&](int c) {
        int kk = c * 64;
        #pragma unroll
        for (int i = 0; i < 8; i++) {
            int row = y_row + i * 16;
            yreg[i] = *(const float4*)(Ybase + (size_t)row * O1 + kk + y_seg * 4);
        }
    };
    auto storeB1 = [&](int c, int buf) {
        int kk = c * 64;
        uint32_t Bh = sb + buf * 4 * TS + 2 * TS;
        float sc[4], sh[4];
        #pragma unroll
        for (int j = 0; j < 4; j++) {
            sc[j] = g_scale0[kk + y_seg * 4 + j];
            sh[j] = g_shift0[kk + y_seg * 4 + j];
        }
        #pragma unroll
        for (int i = 0; i < 8; i++) {
            int row = y_row + i * 16;
            float r[4] = {yreg[i].x, yreg[i].y, yreg[i].z, yreg[i].w};
            uint32_t hp[2], lp[2];
            #pragma unroll
            for (int j = 0; j < 2; j++) {
                __nv_bfloat16 h0, l0, h1, l1;
                split_bf16(fmaxf(fmaf(r[2*j],   sc[2*j],   sh[2*j]),   0.f), h0, l0);
                split_bf16(fmaxf(fmaf(r[2*j+1], sc[2*j+1], sh[2*j+1]), 0.f), h1, l1);
                hp[j] = (uint32_t)__bfloat16_as_ushort(h0) | ((uint32_t)__bfloat16_as_ushort(h1) << 16);
                lp[j] = (uint32_t)__bfloat16_as_ushort(l0) | ((uint32_t)__bfloat16_as_ushort(l1) << 16);
            }
            uint32_t d = (uint32_t)(row * 144 + y_seg * 8);
            *(uint2*)(smem + (Bh - sb) + d)      = make_uint2(hp[0], hp[1]);
            *(uint2*)(smem + (Bh - sb) + TS + d) = make_uint2(lp[0], lp[1]);
        }
    };

    auto mma_set = [&](uint32_t Aoff, uint32_t Boff) {
        uint32_t A  = sb + Aoff + (uint32_t)(m_off * 144) + lm_off;
        uint32_t Bf = sb + Boff + (uint32_t)(n_off * 144) + lm_off;
        #pragma unroll
        for (int kst = 0; kst < 4; kst++) {
            uint32_t af[4][4], bf[2][4];
            #pragma unroll
            for (int mi = 0; mi < 4; mi++)
                ldmx4(A + (uint32_t)(mi * 16 * 144 + kst * 32),
                      af[mi][0], af[mi][1], af[mi][2], af[mi][3]);
            #pragma unroll
            for (int nj = 0; nj < 2; nj++)
                ldmx4(Bf + (uint32_t)(nj * 16 * 144 + kst * 32),
                      bf[nj][0], bf[nj][1], bf[nj][2], bf[nj][3]);
            #pragma unroll
            for (int mi = 0; mi < 4; mi++)
                #pragma unroll
                for (int ni = 0; ni < 4; ni++)
                    mma16816(acc[mi][ni], af[mi],
                             bf[ni >> 1][ni & 1], bf[ni >> 1][(ni & 1) + 2]);
        }
    };

    // ---- pipelined chunk loop ----
    if (LAYER == 0) {
        issue_chunk_A(0, 0); issue_chunk_B0(0, 0); cp_commit();
        for (int c = 0; c < NCH; c++) {
            int buf = c & 1;
            if (c + 1 < NCH) {
                issue_chunk_A(c + 1, buf ^ 1); issue_chunk_B0(c + 1, buf ^ 1); cp_commit();
                cp_wait<1>();
            } else cp_wait<0>();
            __syncthreads();
            uint32_t base = (uint32_t)(buf * 4 * TS);
            mma_set(base, base + 2 * TS);          // Wh * Xh
            mma_set(base, base + 3 * TS);          // Wh * Xl
            mma_set(base + TS, base + 2 * TS);     // Wl * Xh
            __syncthreads();
        }
    } else {
        issue_chunk_A(0, 0); cp_commit();
        loadB1(0);
        for (int c = 0; c < NCH; c++) {
            int buf = c & 1;
            storeB1(c, buf);
            if (c + 1 < NCH) {
                issue_chunk_A(c + 1, buf ^ 1); cp_commit();
                loadB1(c + 1);                     // LDG overlaps this chunk's MMAs
                cp_wait<1>();
            } else cp_wait<0>();
            __syncthreads();
            uint32_t base = (uint32_t)(buf * 4 * TS);
            mma_set(base, base + 2 * TS);
            mma_set(base, base + 3 * TS);
            mma_set(base + TS, base + 2 * TS);
            __syncthreads();
        }
    }

    // ---- epilogue: stage D to SMEM [o][n] stride 129, then stats + stores ----
    float* sD = (float*)smem;
    #pragma unroll
    for (int mi = 0; mi < 4; mi++) {
        int r0 = m_off + mi * 16 + (lane >> 2);
        #pragma unroll
        for (int ni = 0; ni < 4; ni++) {
            int cc = n_off + ni * 8 + (lane & 3) * 2;
            sD[r0 * 129 + cc]           = acc[mi][ni][0];
            sD[r0 * 129 + cc + 1]       = acc[mi][ni][1];
            sD[(r0 + 8) * 129 + cc]     = acc[mi][ni][2];
            sD[(r0 + 8) * 129 + cc + 1] = acc[mi][ni][3];
        }
    }
    __syncthreads();

    {
        int o = tid & 127;
        int nlo = (tid >> 7) * 64;
        float bi = bias[o0 + o];
        float s = 0.f, s2 = 0.f;
        #pragma unroll 4
        for (int n = nlo; n < nlo + 64; n++) {
            float v = sD[o * 129 + n] + bi;
            s += v;
            s2 = fmaf(v, v, s2);
        }
        float* gs = (LAYER == 0) ? g_sum0 : g_sum1;
        float* gq = (LAYER == 0) ? g_sq0  : g_sq1;
        atomicAdd(&gs[o0 + o], s);
        atomicAdd(&gq[o0 + o], s2);
    }

    if (LAYER == 0) {
        for (int e = tid; e < 128 * 128; e += 256) {
            int n = e >> 7, o = e & 127;
            g_y1T[((size_t)b * N1 + n0 + n) * O1 + o0 + o] = sD[o * 129 + n] + bias[o0 + o];
        }
    } else {
        for (int e = tid; e < 128 * 128; e += 256) {
            int o = e >> 7, n = e & 127;
            g_y2[((size_t)b * O2 + o) * N1 + n0 + n] = sD[o * 129 + n] + bias[o];
        }
    }
}

// ---------------- BN finalize ----------------
template <int LAYER>
__global__ void bn_finalize_kernel(const float* __restrict__ gamma,
                                   const float* __restrict__ beta) {
    constexpr int O = (LAYER == 0) ? O1 : O2;
    int o = threadIdx.x;
    if (o < O) {
        const float inv = 1.0f / (float)P_TOTAL;
        float su = (LAYER == 0) ? g_sum0[o] : g_sum1[o];
        float sq = (LAYER == 0) ? g_sq0[o]  : g_sq1[o];
        float mu  = su * inv;
        float var = sq * inv - mu * mu;
        float sc  = gamma[o] * rsqrtf(var + BN_EPS);
        if (LAYER == 0) { g_scale0[o] = sc; g_shift0[o] = beta[o] - mu * sc; }
        else            { g_scale1[o] = sc; g_shift1[o] = beta[o] - mu * sc; }
    }
}

// ---------------- final BN1 + ReLU -> output ----------------
__global__ __launch_bounds__(256) void final_kernel(float* __restrict__ out) {
    int i = blockIdx.x * blockDim.x + threadIdx.x;
    float4 v = ((const float4*)g_y2)[i];
    int c = ((i * 4) / N1) & (O2 - 1);
    float sc = g_scale1[c], sh = g_shift1[c];
    v.x = fmaxf(fmaf(v.x, sc, sh), 0.f);
    v.y = fmaxf(fmaf(v.y, sc, sh), 0.f);
    v.z = fmaxf(fmaf(v.z, sc, sh), 0.f);
    v.w = fmaxf(fmaf(v.w, sc, sh), 0.f);
    ((float4*)out)[i] = v;
}

// ---------------- launch ----------------
extern "C" void kernel_launch(void* const* d_in, const int* in_sizes, int n_in,
                              void* d_out, int out_size) {
    const float* xyz1    = (const float*)d_in[0];
    const float* xyz2    = (const float*)d_in[1];
    const float* points1 = (const float*)d_in[2];
    const float* points2 = (const float*)d_in[3];
    const float* w0  = (const float*)d_in[4];
    const float* b0  = (const float*)d_in[5];
    const float* ga0 = (const float*)d_in[6];
    const float* be0 = (const float*)d_in[7];
    const float* w1  = (const float*)d_in[8];
    const float* b1  = (const float*)d_in[9];
    const float* ga1 = (const float*)d_in[10];
    const float* be1 = (const float*)d_in[11];
    float* out = (float*)d_out;

    cudaFuncSetAttribute(conv_mma_kernel<0>, cudaFuncAttributeMaxDynamicSharedMemorySize, SMEM_MMA);
    cudaFuncSetAttribute(conv_mma_kernel<1>, cudaFuncAttributeMaxDynamicSharedMemorySize, SMEM_MMA);

    __nv_bfloat16 *w0h, *w0l, *w1h, *w1l;
    cudaGetSymbolAddress((void**)&w0h, g_w0h);
    cudaGetSymbolAddress((void**)&w0l, g_w0l);
    cudaGetSymbolAddress((void**)&w1h, g_w1h);
    cudaGetSymbolAddress((void**)&w1l, g_w1l);

    init_stats_kernel<<<1, 256>>>();
    split_w_kernel<<<(O1 * KIN1 + 255) / 256, 256>>>(w0, w0h, w0l, O1 * KIN1);
    split_w_kernel<<<(O2 * O1 + 255) / 256, 256>>>(w1, w1h, w1l, O2 * O1);
    transpose_p2_kernel<<<dim3(N2 / 32, C2 / 32, BB), dim3(32, 8)>>>(points2);
    transpose_p1_kernel<<<dim3(N1 / 32, C1 / 32, BB), dim3(32, 8)>>>(points1);
    knn_kernel<<<BB * (N1 / 128), 128>>>(xyz1, xyz2);
    interp_kernel<<<BB * (N1 / 32), 256>>>();
    conv_mma_kernel<0><<<dim3(BB * (N1 / 128), O1 / 128), 256, SMEM_MMA>>>(b0);
    bn_finalize_kernel<0><<<1, 256>>>(ga0, be0);
    conv_mma_kernel<1><<<dim3(BB * (N1 / 128), O2 / 128), 256, SMEM_MMA>>>(b1);
    bn_finalize_kernel<1><<<1, 128>>>(ga1, be1);
    final_kernel<<<(BB * O2 * N1 / 4) / 256, 256>>>(out);
}

// round 6
// speedup vs baseline: 1.4193x; 1.4193x over previous
#include <cuda_runtime.h>
#include <cuda_fp16.h>
#include <math.h>
#include <stdint.h>

#define BB 8
#define N1 8192
#define N2 2048
#define C1 128
#define C2 256
#define KIN1 384
#define O1 256
#define O2 128
#define BN_EPS 1e-5f
#define MIN_DIST 1e-10f
#define P_TOTAL (BB * N1)

// ---------------- scratch (no allocations allowed) ----------------
__device__ float g_p2T[BB * N2 * C2];                 // points2 transposed [B][N2][C2]
__device__ int   g_knn_idx[BB * N1 * 3];
__device__ float g_knn_w[BB * N1 * 3];
__device__ __half g_w0[O1 * KIN1];
__device__ __half g_w1[O2 * O1];
__device__ __half g_x0[BB * N1 * KIN1];               // conv0 B operand [n][k] fp16
__device__ __half g_x2[BB * N1 * O1];                 // conv1 B operand [n][k] fp16
__device__ float g_y1T[BB * N1 * O1];                 // conv0 out (pre-BN), point-major [n][o]
__device__ float g_y2[BB * O2 * N1];                  // conv1 out (pre-BN), channel-major [o][n]
__device__ float g_sum0[O1], g_sq0[O1], g_sum1[O2], g_sq1[O2];
__device__ float g_scale0[O1], g_shift0[O1], g_scale1[O2], g_shift1[O2];

// ---------------- helpers ----------------
__device__ __forceinline__ uint32_t smem_u32(const void* p) {
    return (uint32_t)__cvta_generic_to_shared(p);
}
__device__ __forceinline__ void cp16(uint32_t dst, const void* src) {
    asm volatile("cp.async.ca.shared.global [%0], [%1], 16;" :: "r"(dst), "l"(src));
}
__device__ __forceinline__ void cp_commit() {
    asm volatile("cp.async.commit_group;" ::: "memory");
}
template <int N>
__device__ __forceinline__ void cp_wait() {
    asm volatile("cp.async.wait_group %0;" :: "n"(N) : "memory");
}
__device__ __forceinline__ void ldmx4(uint32_t a, uint32_t& r0, uint32_t& r1,
                                      uint32_t& r2, uint32_t& r3) {
    asm volatile("ldmatrix.sync.aligned.m8n8.x4.shared.b16 {%0,%1,%2,%3}, [%4];"
                 : "=r"(r0), "=r"(r1), "=r"(r2), "=r"(r3) : "r"(a));
}
__device__ __forceinline__ void mma16816(float* c, const uint32_t* a,
                                         uint32_t b0, uint32_t b1) {
    asm volatile("mma.sync.aligned.m16n8k16.row.col.f32.f16.f16.f32 "
                 "{%0,%1,%2,%3},{%4,%5,%6,%7},{%8,%9},{%0,%1,%2,%3};"
                 : "+f"(c[0]), "+f"(c[1]), "+f"(c[2]), "+f"(c[3])
                 : "r"(a[0]), "r"(a[1]), "r"(a[2]), "r"(a[3]), "r"(b0), "r"(b1));
}

// ---------------- stats zero (graph replays!) ----------------
__global__ void init_stats_kernel() {
    int t = threadIdx.x;
    if (t < O1) { g_sum0[t] = 0.f; g_sq0[t] = 0.f; }
    if (t < O2) { g_sum1[t] = 0.f; g_sq1[t] = 0.f; }
}

// ---------------- weight convert fp32 -> fp16 ----------------
__global__ void cvt_w_kernel(const float* __restrict__ src,
                             __half* __restrict__ dst, int n) {
    int i = blockIdx.x * blockDim.x + threadIdx.x;
    if (i < n) dst[i] = __float2half_rn(src[i]);
}

// ---------------- transpose points2 [B,C2,N2] -> [B,N2,C2] ----------------
__global__ void transpose_p2_kernel(const float* __restrict__ p2) {
    __shared__ float tile[32][33];
    int b = blockIdx.z, c0 = blockIdx.y * 32, n0 = blockIdx.x * 32;
    int tx = threadIdx.x, ty = threadIdx.y;
    #pragma unroll
    for (int i = ty; i < 32; i += 8)
        tile[i][tx] = p2[(size_t)b * C2 * N2 + (size_t)(c0 + i) * N2 + n0 + tx];
    __syncthreads();
    #pragma unroll
    for (int i = ty; i < 32; i += 8)
        g_p2T[(size_t)b * N2 * C2 + (size_t)(n0 + i) * C2 + c0 + tx] = tile[tx][i];
}

// ---------------- transpose+cvt points1 [B,C1,N1] -> x0 [n][0..127] fp16 ----------------
__global__ void transpose_p1_kernel(const float* __restrict__ p1) {
    __shared__ float tile[32][33];
    int b = blockIdx.z, c0 = blockIdx.y * 32, n0 = blockIdx.x * 32;
    int tx = threadIdx.x, ty = threadIdx.y;
    #pragma unroll
    for (int i = ty; i < 32; i += 8)
        tile[i][tx] = p1[(size_t)b * C1 * N1 + (size_t)(c0 + i) * N1 + n0 + tx];
    __syncthreads();
    #pragma unroll
    for (int i = ty; i < 32; i += 8)
        g_x0[((size_t)b * N1 + n0 + i) * KIN1 + c0 + tx] = __float2half_rn(tile[tx][i]);
}

// ---------------- 3-NN ----------------
__global__ __launch_bounds__(128) void knn_kernel(const float* __restrict__ xyz1,
                                                  const float* __restrict__ xyz2) {
    __shared__ float4 s_p[N2];
    int b  = blockIdx.x >> 6;
    int n0 = (blockIdx.x & 63) << 7;
    const float* x2 = xyz2 + (size_t)b * N2 * 3;
    for (int j = threadIdx.x; j < N2; j += 128) {
        float px = x2[j * 3], py = x2[j * 3 + 1], pz = x2[j * 3 + 2];
        s_p[j] = make_float4(px, py, pz, px * px + py * py + pz * pz);
    }
    __syncthreads();
    int n = n0 + threadIdx.x;
    const float* q = xyz1 + ((size_t)b * N1 + n) * 3;
    float qx = q[0], qy = q[1], qz = q[2];
    float qn = qx * qx + qy * qy + qz * qz;
    float d0 = 3.4e38f, d1 = 3.4e38f, d2 = 3.4e38f;
    int   i0 = 0, i1 = 0, i2 = 0;
    #pragma unroll 4
    for (int j = 0; j < N2; j++) {
        float4 p = s_p[j];
        float t  = fmaf(qx, p.x, fmaf(qy, p.y, qz * p.z));
        float sq = qn + p.w - 2.f * t;
        if (sq < d2) {
            if (sq < d1) {
                d2 = d1; i2 = i1;
                if (sq < d0) { d1 = d0; i1 = i0; d0 = sq; i0 = j; }
                else         { d1 = sq; i1 = j; }
            } else { d2 = sq; i2 = j; }
        }
    }
    float e0 = fmaxf(sqrtf(fmaxf(d0, 0.f)), MIN_DIST);
    float e1 = fmaxf(sqrtf(fmaxf(d1, 0.f)), MIN_DIST);
    float e2 = fmaxf(sqrtf(fmaxf(d2, 0.f)), MIN_DIST);
    float w0 = 1.f / e0, w1 = 1.f / e1, w2 = 1.f / e2;
    float inv = 1.f / (w0 + w1 + w2);
    size_t on = ((size_t)b * N1 + n) * 3;
    g_knn_idx[on] = i0; g_knn_idx[on + 1] = i1; g_knn_idx[on + 2] = i2;
    g_knn_w[on] = w0 * inv; g_knn_w[on + 1] = w1 * inv; g_knn_w[on + 2] = w2 * inv;
}

// ---------------- interpolation -> x0 [n][128..383] fp16 ----------------
__global__ __launch_bounds__(256) void interp_kernel() {
    __shared__ int   s_idx[96];
    __shared__ float s_w[96];
    int b  = blockIdx.x >> 8;
    int n0 = (blockIdx.x & 255) << 5;
    int t  = threadIdx.x;
    if (t < 96) {
        size_t base = ((size_t)b * N1 + n0) * 3 + t;
        s_idx[t] = g_knn_idx[base];
        s_w[t]   = g_knn_w[base];
    }
    __syncthreads();
    int c = t;
    #pragma unroll 4
    for (int p = 0; p < 32; p++) {
        int k = p * 3;
        const float* r0 = g_p2T + ((size_t)b * N2 + s_idx[k + 0]) * C2 + c;
        const float* r1 = g_p2T + ((size_t)b * N2 + s_idx[k + 1]) * C2 + c;
        const float* r2 = g_p2T + ((size_t)b * N2 + s_idx[k + 2]) * C2 + c;
        float v = fmaf(s_w[k], *r0, fmaf(s_w[k + 1], *r1, s_w[k + 2] * (*r2)));
        g_x0[((size_t)b * N1 + n0 + p) * KIN1 + C1 + c] = __float2half_rn(v);
    }
}

// ---------------- mma.sync conv, single-pass fp16 ----------------
// CTA 128x128, 8 warps (2x4 -> 64x32 each), K-chunk 64, cp.async double buffer.
// SMEM rows padded to 72 fp16 (144 B) -> conflict-free ldmatrix.
#define SM_A0 0
#define SM_A1 18432
#define SM_B0 36864
#define SM_B1 55296
#define SMEM_MMA 73728

template <int LAYER>
__global__ void __launch_bounds__(256, 1) conv_mma_kernel(const float* __restrict__ bias) {
    constexpr int K   = (LAYER == 0) ? KIN1 : O1;
    constexpr int NCH = K / 64;
    extern __shared__ char smem[];
    uint32_t sb = smem_u32(smem);

    int tid  = threadIdx.x;
    int lane = tid & 31, wid = tid >> 5;
    int m_off = (wid >> 2) * 64;     // warp m-origin (o)
    int n_off = (wid & 3) * 32;      // warp n-origin (points)
    int b  = blockIdx.x >> 6;
    int n0 = (blockIdx.x & 63) << 7;
    int o0 = blockIdx.y << 7;

    const __half* Wbase = ((LAYER == 0) ? g_w0 : g_w1) + (size_t)o0 * K;
    const __half* Xbase = ((LAYER == 0) ? g_x0 : g_x2) + ((size_t)b * N1 + n0) * K;

    uint32_t lm_off = (uint32_t)(((lane & 7) + ((lane >> 3) & 1) * 8) * 144 + (lane >> 4) * 16);

    float acc[4][4][4];
    #pragma unroll
    for (int mi = 0; mi < 4; mi++)
        #pragma unroll
        for (int ni = 0; ni < 4; ni++)
            #pragma unroll
            for (int r = 0; r < 4; r++) acc[mi][ni][r] = 0.f;

    int ld_row = tid >> 3;           // 32 rows per i-step
    int ld_seg = tid & 7;

    auto issue_chunk = [&](int c, int buf) {
        int kk = c * 64;
        uint32_t A  = sb + (buf ? SM_A1 : SM_A0);
        uint32_t Bf = sb + (buf ? SM_B1 : SM_B0);
        #pragma unroll
        for (int i = 0; i < 4; i++) {
            int row = ld_row + i * 32;
            uint32_t d = (uint32_t)(row * 144 + ld_seg * 16);
            cp16(A + d,  Wbase + (size_t)row * K + kk + ld_seg * 8);
            cp16(Bf + d, Xbase + (size_t)row * K + kk + ld_seg * 8);
        }
        cp_commit();
    };

    issue_chunk(0, 0);
    for (int c = 0; c < NCH; c++) {
        int buf = c & 1;
        if (c + 1 < NCH) { issue_chunk(c + 1, buf ^ 1); cp_wait<1>(); }
        else             { cp_wait<0>(); }
        __syncthreads();

        uint32_t A  = sb + (buf ? SM_A1 : SM_A0) + (uint32_t)(m_off * 144) + lm_off;
        uint32_t Bf = sb + (buf ? SM_B1 : SM_B0) + (uint32_t)(n_off * 144) + lm_off;
        #pragma unroll
        for (int kst = 0; kst < 4; kst++) {
            uint32_t af[4][4], bf[2][4];
            #pragma unroll
            for (int mi = 0; mi < 4; mi++)
                ldmx4(A + (uint32_t)(mi * 16 * 144 + kst * 32),
                      af[mi][0], af[mi][1], af[mi][2], af[mi][3]);
            #pragma unroll
            for (int nj = 0; nj < 2; nj++)
                ldmx4(Bf + (uint32_t)(nj * 16 * 144 + kst * 32),
                      bf[nj][0], bf[nj][1], bf[nj][2], bf[nj][3]);
            #pragma unroll
            for (int mi = 0; mi < 4; mi++)
                #pragma unroll
                for (int ni = 0; ni < 4; ni++)
                    mma16816(acc[mi][ni], af[mi],
                             bf[ni >> 1][ni & 1], bf[ni >> 1][(ni & 1) + 2]);
        }
        __syncthreads();
    }

    // ---- epilogue: stage D to SMEM [o][n] stride 129, then stats + stores ----
    float* sD = (float*)smem;
    #pragma unroll
    for (int mi = 0; mi < 4; mi++) {
        int r0 = m_off + mi * 16 + (lane >> 2);
        #pragma unroll
        for (int ni = 0; ni < 4; ni++) {
            int cc = n_off + ni * 8 + (lane & 3) * 2;
            sD[r0 * 129 + cc]           = acc[mi][ni][0];
            sD[r0 * 129 + cc + 1]       = acc[mi][ni][1];
            sD[(r0 + 8) * 129 + cc]     = acc[mi][ni][2];
            sD[(r0 + 8) * 129 + cc + 1] = acc[mi][ni][3];
        }
    }
    __syncthreads();

    {
        int o = tid & 127;
        int nlo = (tid >> 7) * 64;
        float bi = bias[o0 + o];
        float s = 0.f, s2 = 0.f;
        #pragma unroll 4
        for (int n = nlo; n < nlo + 64; n++) {
            float v = sD[o * 129 + n] + bi;
            s += v;
            s2 = fmaf(v, v, s2);
        }
        float* gs = (LAYER == 0) ? g_sum0 : g_sum1;
        float* gq = (LAYER == 0) ? g_sq0  : g_sq1;
        atomicAdd(&gs[o0 + o], s);
        atomicAdd(&gq[o0 + o], s2);
    }

    if (LAYER == 0) {
        for (int e = tid; e < 128 * 128; e += 256) {
            int n = e >> 7, o = e & 127;
            g_y1T[((size_t)b * N1 + n0 + n) * O1 + o0 + o] = sD[o * 129 + n] + bias[o0 + o];
        }
    } else {
        for (int e = tid; e < 128 * 128; e += 256) {
            int o = e >> 7, n = e & 127;
            g_y2[((size_t)b * O2 + o) * N1 + n0 + n] = sD[o * 129 + n] + bias[o];
        }
    }
}

// ---------------- BN finalize ----------------
template <int LAYER>
__global__ void bn_finalize_kernel(const float* __restrict__ gamma,
                                   const float* __restrict__ beta) {
    constexpr int O = (LAYER == 0) ? O1 : O2;
    int o = threadIdx.x;
    if (o < O) {
        const float inv = 1.0f / (float)P_TOTAL;
        float su = (LAYER == 0) ? g_sum0[o] : g_sum1[o];
        float sq = (LAYER == 0) ? g_sq0[o]  : g_sq1[o];
        float mu  = su * inv;
        float var = sq * inv - mu * mu;
        float sc  = gamma[o] * rsqrtf(var + BN_EPS);
        if (LAYER == 0) { g_scale0[o] = sc; g_shift0[o] = beta[o] - mu * sc; }
        else            { g_scale1[o] = sc; g_shift1[o] = beta[o] - mu * sc; }
    }
}

// ---------------- midpass: y1T -> BN0+ReLU -> fp16 x2 ----------------
__global__ __launch_bounds__(256) void midpass_kernel() {
    size_t i4 = (size_t)blockIdx.x * 256 + threadIdx.x;   // float4 index
    float4 v = ((const float4*)g_y1T)[i4];
    int c0 = (int)((i4 * 4) & (O1 - 1));
    float r[4] = {v.x, v.y, v.z, v.w};
    unsigned short h[4];
    #pragma unroll
    for (int j = 0; j < 4; j++) {
        float x = fmaxf(fmaf(r[j], g_scale0[c0 + j], g_shift0[c0 + j]), 0.f);
        h[j] = __half_as_ushort(__float2half_rn(x));
    }
    ((uint2*)g_x2)[i4] = make_uint2((uint32_t)h[0] | ((uint32_t)h[1] << 16),
                                    (uint32_t)h[2] | ((uint32_t)h[3] << 16));
}

// ---------------- final BN1 + ReLU -> output ----------------
__global__ __launch_bounds__(256) void final_kernel(float* __restrict__ out) {
    int i = blockIdx.x * blockDim.x + threadIdx.x;
    float4 v = ((const float4*)g_y2)[i];
    int c = ((i * 4) / N1) & (O2 - 1);
    float sc = g_scale1[c], sh = g_shift1[c];
    v.x = fmaxf(fmaf(v.x, sc, sh), 0.f);
    v.y = fmaxf(fmaf(v.y, sc, sh), 0.f);
    v.z = fmaxf(fmaf(v.z, sc, sh), 0.f);
    v.w = fmaxf(fmaf(v.w, sc, sh), 0.f);
    ((float4*)out)[i] = v;
}

// ---------------- launch ----------------
extern "C" void kernel_launch(void* const* d_in, const int* in_sizes, int n_in,
                              void* d_out, int out_size) {
    const float* xyz1    = (const float*)d_in[0];
    const float* xyz2    = (const float*)d_in[1];
    const float* points1 = (const float*)d_in[2];
    const float* points2 = (const float*)d_in[3];
    const float* w0  = (const float*)d_in[4];
    const float* b0  = (const float*)d_in[5];
    const float* ga0 = (const float*)d_in[6];
    const float* be0 = (const float*)d_in[7];
    const float* w1  = (const float*)d_in[8];
    const float* b1  = (const float*)d_in[9];
    const float* ga1 = (const float*)d_in[10];
    const float* be1 = (const float*)d_in[11];
    float* out = (float*)d_out;

    cudaFuncSetAttribute(conv_mma_kernel<0>, cudaFuncAttributeMaxDynamicSharedMemorySize, SMEM_MMA);
    cudaFuncSetAttribute(conv_mma_kernel<1>, cudaFuncAttributeMaxDynamicSharedMemorySize, SMEM_MMA);

    __half *dw0, *dw1;
    cudaGetSymbolAddress((void**)&dw0, g_w0);
    cudaGetSymbolAddress((void**)&dw1, g_w1);

    init_stats_kernel<<<1, 256>>>();
    cvt_w_kernel<<<(O1 * KIN1 + 255) / 256, 256>>>(w0, dw0, O1 * KIN1);
    cvt_w_kernel<<<(O2 * O1 + 255) / 256, 256>>>(w1, dw1, O2 * O1);
    transpose_p2_kernel<<<dim3(N2 / 32, C2 / 32, BB), dim3(32, 8)>>>(points2);
    transpose_p1_kernel<<<dim3(N1 / 32, C1 / 32, BB), dim3(32, 8)>>>(points1);
    knn_kernel<<<BB * (N1 / 128), 128>>>(xyz1, xyz2);
    interp_kernel<<<BB * (N1 / 32), 256>>>();
    conv_mma_kernel<0><<<dim3(BB * (N1 / 128), O1 / 128), 256, SMEM_MMA>>>(b0);
    bn_finalize_kernel<0><<<1, 256>>>(ga0, be0);
    midpass_kernel<<<(BB * N1 * O1 / 4) / 256, 256>>>();
    conv_mma_kernel<1><<<dim3(BB * (N1 / 128), O2 / 128), 256, SMEM_MMA>>>(b1);
    bn_finalize_kernel<1><<<1, 128>>>(ga1, be1);
    final_kernel<<<(BB * O2 * N1 / 4) / 256, 256>>>(out);
}